// round 9
// baseline (speedup 1.0000x reference)
#include <cuda_runtime.h>
#include <cstdint>

// VersatileConvSE3  E=16384, C=O=32, D=S=16, F=44, M=32
#define E_TOT 16384
#define NE    16
#define NTHR  512
#define NBLK  (E_TOT / NE)

typedef unsigned long long u64;
#define FMA2(d,a,b,c) asm("fma.rn.f32x2 %0, %1, %2, %3;" : "=l"(d) : "l"(a), "l"(b), "l"(c))
__device__ __forceinline__ u64 pk2(float a, float b) {
    u64 r; asm("mov.b64 %0, {%1, %2};" : "=l"(r) : "f"(a), "f"(b)); return r;
}

__device__ float g_H[E_TOT * 32];

__device__ __forceinline__ float warp_sum(float v) {
    v += __shfl_xor_sync(0xffffffffu, v, 16);
    v += __shfl_xor_sync(0xffffffffu, v, 8);
    v += __shfl_xor_sync(0xffffffffu, v, 4);
    v += __shfl_xor_sync(0xffffffffu, v, 2);
    v += __shfl_xor_sync(0xffffffffu, v, 1);
    return v;
}

__global__ __launch_bounds__(256) void mlp_kernel(
    const float* __restrict__ inv,
    const float* __restrict__ w1, const float* __restrict__ b1,
    const float* __restrict__ g1, const float* __restrict__ be1,
    const float* __restrict__ w2, const float* __restrict__ b2,
    const float* __restrict__ g2, const float* __restrict__ be2)
{
    const int e = blockIdx.x * 8 + (threadIdx.x >> 5);
    const int lane = threadIdx.x & 31;
    const float* x = inv + e * 16;
    float y = b1[lane];
    #pragma unroll
    for (int d = 0; d < 16; ++d) y += x[d] * w1[lane * 16 + d];
    float mu  = warp_sum(y) * (1.0f/32.0f);
    float dz  = y - mu;
    float var = warp_sum(dz*dz) * (1.0f/32.0f);
    float h1  = fmaxf(dz * rsqrtf(var + 1e-5f) * g1[lane] + be1[lane], 0.0f);
    float y2 = b2[lane];
    #pragma unroll
    for (int m = 0; m < 32; ++m)
        y2 += __shfl_sync(0xffffffffu, h1, m) * w2[lane * 32 + m];
    mu  = warp_sum(y2) * (1.0f/32.0f);
    dz  = y2 - mu;
    var = warp_sum(dz*dz) * (1.0f/32.0f);
    g_H[e * 32 + lane] = fmaxf(dz * rsqrtf(var + 1e-5f) * g2[lane] + be2[lane], 0.0f);
}

// smem float offsets
#define OF_H    0        // [m32][e16]                  512
#define OF_BAS  512      // [e16][d16][s16]             4096
#define OF_T    4608     // [c32] str 324, e str 20     10368
#define OF_RW   14976    // [row1024][18]               18432
#define OF_W3   33408    // [lrow512][36]               18432
#define SMEM_FLOATS 51840
#define T_CS 324

__global__ __launch_bounds__(NTHR, 1) void conv_kernel(
    const float* __restrict__ feat,
    const float* __restrict__ basis,
    const float* __restrict__ w3,
    float* __restrict__ out)
{
    extern __shared__ __align__(16) float sm[];
    const int tid = threadIdx.x;
    const int e0  = blockIdx.x * NE;

    // T-gen roles: (e, c-pair, s-half)
    const int tg_e  = tid >> 5;
    const int tg_cp = (tid & 31) >> 1;
    const int tg_sh = tid & 1;
    // half-0 stager (all threads)
    const int s_r = tid >> 3, s_k = tid & 7;
    // Phase A (tid < 256): 4 rows x 8 e
    const int a_la = tid & 127, a_eh = (tid >> 7) & 1;
    // Phase B (tid >= 256): (e, o-quad, s-half)
    const int bj   = tid & 255;
    const int b_e  = bj & 15, b_oq = (bj >> 4) & 7, b_sh = bj >> 7;
    // half-1 stager (tid >= 256)
    const int h_k = bj & 7, h_slot = bj >> 3;

    // stage H transposed [m][e]
    sm[OF_H + (tid & 31) * 16 + (tid >> 5)] = g_H[(size_t)(e0 + (tid >> 5)) * 32 + (tid & 31)];

    // feat -> regs: two c rows (c = 2*cp, 2*cp+1)
    float fr0[16], fr1[16];
    {
        const float4* fa = (const float4*)(feat + ((size_t)(e0 + tg_e) * 32 + tg_cp * 2) * 16);
        const float4* fb = fa + 4;
        #pragma unroll
        for (int i = 0; i < 4; ++i) {
            float4 v = __ldg(fa + i);
            fr0[4*i] = v.x; fr0[4*i+1] = v.y; fr0[4*i+2] = v.z; fr0[4*i+3] = v.w;
            float4 w = __ldg(fb + i);
            fr1[4*i] = w.x; fr1[4*i+1] = w.y; fr1[4*i+2] = w.z; fr1[4*i+3] = w.w;
        }
    }

    // basis prefetch (f=0)
    const float* bas_base = basis + (((size_t)(e0 + (tid >> 5)) * 16 + ((tid >> 1) & 15)) * 44) * 16 + (tid & 1) * 8;
    float4 bpre0 = __ldg((const float4*)bas_base);
    float4 bpre1 = __ldg((const float4*)bas_base + 1);

    // Phase B accumulators: 4 o x 8 s
    u64 acc[4][4];
    #pragma unroll
    for (int i = 0; i < 4; ++i)
        #pragma unroll
        for (int j = 0; j < 4; ++j) acc[i][j] = 0ull;

    __syncthreads();

    // Phase A: 4 rows (la+128i) x 8 e (half eh), 32 m
    #define PHASE_A(HALF)                                                         \
    {                                                                             \
        u64 A_[4][4];                                                             \
        _Pragma("unroll")                                                         \
        for (int i = 0; i < 4; ++i) { A_[i][0]=0ull; A_[i][1]=0ull; A_[i][2]=0ull; A_[i][3]=0ull; } \
        const float* hb = sm + OF_H + a_eh * 8;                                   \
        const float* wb = sm + OF_W3 + a_la * 36;                                 \
        _Pragma("unroll")                                                         \
        for (int mq = 0; mq < 8; ++mq) {                                          \
            float4 wq[4];                                                         \
            _Pragma("unroll")                                                     \
            for (int i = 0; i < 4; ++i) wq[i] = *(const float4*)(wb + i * (128*36) + mq * 4); \
            _Pragma("unroll")                                                     \
            for (int mm = 0; mm < 4; ++mm) {                                      \
                const int m = mq * 4 + mm;                                        \
                ulonglong2 ha = *(const ulonglong2*)(hb + m * 16);                \
                ulonglong2 hc = *(const ulonglong2*)(hb + m * 16 + 4);            \
                const float wv0 = (mm==0)?wq[0].x:(mm==1)?wq[0].y:(mm==2)?wq[0].z:wq[0].w; \
                const float wv1 = (mm==0)?wq[1].x:(mm==1)?wq[1].y:(mm==2)?wq[1].z:wq[1].w; \
                const float wv2 = (mm==0)?wq[2].x:(mm==1)?wq[2].y:(mm==2)?wq[2].z:wq[2].w; \
                const float wv3 = (mm==0)?wq[3].x:(mm==1)?wq[3].y:(mm==2)?wq[3].z:wq[3].w; \
                u64 p;                                                            \
                p = pk2(wv0, wv0);                                                \
                FMA2(A_[0][0], p, ha.x, A_[0][0]); FMA2(A_[0][1], p, ha.y, A_[0][1]); \
                FMA2(A_[0][2], p, hc.x, A_[0][2]); FMA2(A_[0][3], p, hc.y, A_[0][3]); \
                p = pk2(wv1, wv1);                                                \
                FMA2(A_[1][0], p, ha.x, A_[1][0]); FMA2(A_[1][1], p, ha.y, A_[1][1]); \
                FMA2(A_[1][2], p, hc.x, A_[1][2]); FMA2(A_[1][3], p, hc.y, A_[1][3]); \
                p = pk2(wv2, wv2);                                                \
                FMA2(A_[2][0], p, ha.x, A_[2][0]); FMA2(A_[2][1], p, ha.y, A_[2][1]); \
                FMA2(A_[2][2], p, hc.x, A_[2][2]); FMA2(A_[2][3], p, hc.y, A_[2][3]); \
                p = pk2(wv3, wv3);                                                \
                FMA2(A_[3][0], p, ha.x, A_[3][0]); FMA2(A_[3][1], p, ha.y, A_[3][1]); \
                FMA2(A_[3][2], p, hc.x, A_[3][2]); FMA2(A_[3][3], p, hc.y, A_[3][3]); \
            }                                                                     \
        }                                                                         \
        _Pragma("unroll")                                                         \
        for (int i = 0; i < 4; ++i) {                                             \
            u64* dp = (u64*)(sm + OF_RW + (size_t)((HALF)*512 + a_la + 128*i) * 18 + a_eh * 8); \
            dp[0] = A_[i][0]; dp[1] = A_[i][1]; dp[2] = A_[i][2]; dp[3] = A_[i][3]; \
        }                                                                         \
    }

    // Phase B body: this thread's fixed o-quad over all 32 c
    #define B_RUN()                                                               \
    {                                                                             \
        const float* rwb = sm + OF_RW;                                            \
        const float* tb  = sm + OF_T + b_e * 20 + b_sh * 8;                       \
        _Pragma("unroll")                                                         \
        for (int c = 0; c < 32; ++c) {                                            \
            const ulonglong2* tp = (const ulonglong2*)(tb + c * T_CS);            \
            ulonglong2 qa = tp[0], qb = tp[1];                                    \
            _Pragma("unroll")                                                     \
            for (int i = 0; i < 4; ++i) {                                         \
                float rv = rwb[(size_t)((b_oq * 4 + i) * 32 + c) * 18 + b_e];     \
                u64 rp = pk2(rv, rv);                                             \
                FMA2(acc[i][0], rp, qa.x, acc[i][0]);                             \
                FMA2(acc[i][1], rp, qa.y, acc[i][1]);                             \
                FMA2(acc[i][2], rp, qb.x, acc[i][2]);                             \
                FMA2(acc[i][3], rp, qb.y, acc[i][3]);                             \
            }                                                                     \
        }                                                                         \
    }

    for (int f = 0; f < 44; ++f) {
        // stage basis slice
        {
            float4* bp = (float4*)(sm + OF_BAS + tid * 8);
            bp[0] = bpre0; bp[1] = bpre1;
        }
        __syncthreads();   // S1
        if (f < 43) {
            const float* bs = bas_base + (size_t)(f + 1) * 16;
            bpre0 = __ldg((const float4*)bs);
            bpre1 = __ldg((const float4*)bs + 1);
        }

        // w3 half-0 LDG (all threads, overlapped by T-gen)
        float4 w_[8];
        #pragma unroll
        for (int i = 0; i < 8; ++i) {
            const int lr = i * 64 + s_r;
            const int o = lr >> 5, c = lr & 31;
            w_[i] = __ldg((const float4*)(w3 + ((size_t)o * 1408 + (size_t)c * 44 + f) * 32 + s_k * 4));
        }

        // T-gen: t[c][s-half] for 2 c, 8 s
        {
            u64 t0[4], t1[4];
            #pragma unroll
            for (int k = 0; k < 4; ++k) { t0[k] = 0ull; t1[k] = 0ull; }
            const float* bb = sm + OF_BAS + tg_e * 256 + tg_sh * 8;
            #pragma unroll
            for (int d = 0; d < 16; ++d) {
                ulonglong2 qa = *(const ulonglong2*)(bb + d * 16);
                ulonglong2 qb = *(const ulonglong2*)(bb + d * 16 + 4);
                u64 fa = pk2(fr0[d], fr0[d]);
                u64 fb = pk2(fr1[d], fr1[d]);
                FMA2(t0[0], fa, qa.x, t0[0]); FMA2(t0[1], fa, qa.y, t0[1]);
                FMA2(t0[2], fa, qb.x, t0[2]); FMA2(t0[3], fa, qb.y, t0[3]);
                FMA2(t1[0], fb, qa.x, t1[0]); FMA2(t1[1], fb, qa.y, t1[1]);
                FMA2(t1[2], fb, qb.x, t1[2]); FMA2(t1[3], fb, qb.y, t1[3]);
            }
            float* tb0 = sm + OF_T + (size_t)(tg_cp * 2) * T_CS + tg_e * 20 + tg_sh * 8;
            float* tb1 = tb0 + T_CS;
            ulonglong2 v;
            v.x = t0[0]; v.y = t0[1]; ((ulonglong2*)tb0)[0] = v;
            v.x = t0[2]; v.y = t0[3]; ((ulonglong2*)(tb0 + 4))[0] = v;
            v.x = t1[0]; v.y = t1[1]; ((ulonglong2*)tb1)[0] = v;
            v.x = t1[2]; v.y = t1[3]; ((ulonglong2*)(tb1 + 4))[0] = v;
        }

        #pragma unroll
        for (int i = 0; i < 8; ++i) {
            const int lr = i * 64 + s_r;
            *(float4*)(sm + OF_W3 + lr * 36 + s_k * 4) = w_[i];
        }
        __syncthreads();   // S2: sW3 half0 + sT ready

        float4 wh_[8];
        if (tid < 256) {
            PHASE_A(0)
        } else {
            // wave-1 LDG of w3 half-1 (hidden under A half0)
            #pragma unroll
            for (int i = 0; i < 8; ++i) {
                const int lr = h_slot + 32 * i;
                const int gr = 512 + lr;
                const int o = gr >> 5, c = gr & 31;
                wh_[i] = __ldg((const float4*)(w3 + ((size_t)o * 1408 + (size_t)c * 44 + f) * 32 + h_k * 4));
            }
        }
        __syncthreads();   // S3: rw half0 ready, sW3 free

        if (tid >= 256) {
            #pragma unroll
            for (int i = 0; i < 8; ++i) {
                const int lr = h_slot + 32 * i;
                *(float4*)(sm + OF_W3 + lr * 36 + h_k * 4) = wh_[i];
            }
            // wave-2
            #pragma unroll
            for (int i = 0; i < 8; ++i) {
                const int lr = h_slot + 32 * (8 + i);
                const int gr = 512 + lr;
                const int o = gr >> 5, c = gr & 31;
                wh_[i] = __ldg((const float4*)(w3 + ((size_t)o * 1408 + (size_t)c * 44 + f) * 32 + h_k * 4));
            }
            #pragma unroll
            for (int i = 0; i < 8; ++i) {
                const int lr = h_slot + 32 * (8 + i);
                *(float4*)(sm + OF_W3 + lr * 36 + h_k * 4) = wh_[i];
            }
        }
        __syncthreads();   // S4: sW3 half1 ready

        if (tid < 256) {
            PHASE_A(1)
        } else if (b_oq < 4) {
            B_RUN()        // B-low: needs only rw rows 0..511 (ready since S3)
        }
        __syncthreads();   // S5: rw half1 ready

        if (tid >= 256 && b_oq >= 4) {
            B_RUN()
        }
    }

    // store (B threads own the output)
    if (tid >= 256) {
        #pragma unroll
        for (int i = 0; i < 4; ++i) {
            const int o = b_oq * 4 + i;
            float* op = out + (((size_t)(e0 + b_e) * 32) + o) * 16 + b_sh * 8;
            ulonglong2 v;
            v.x = acc[i][0]; v.y = acc[i][1]; ((ulonglong2*)op)[0] = v;
            v.x = acc[i][2]; v.y = acc[i][3]; ((ulonglong2*)op)[1] = v;
        }
    }
    #undef PHASE_A
    #undef B_RUN
}

extern "C" void kernel_launch(void* const* d_in, const int* in_sizes, int n_in,
                              void* d_out, int out_size)
{
    const float* features = (const float*)d_in[0];
    const float* inv      = (const float*)d_in[1];
    const float* basis    = (const float*)d_in[2];
    const float* w1  = (const float*)d_in[3];
    const float* b1  = (const float*)d_in[4];
    const float* g1  = (const float*)d_in[5];
    const float* be1 = (const float*)d_in[6];
    const float* w2  = (const float*)d_in[7];
    const float* b2  = (const float*)d_in[8];
    const float* g2  = (const float*)d_in[9];
    const float* be2 = (const float*)d_in[10];
    const float* w3  = (const float*)d_in[11];
    float* out = (float*)d_out;

    cudaFuncSetAttribute(conv_kernel, cudaFuncAttributeMaxDynamicSharedMemorySize,
                         SMEM_FLOATS * (int)sizeof(float));

    mlp_kernel<<<E_TOT / 8, 256>>>(inv, w1, b1, g1, be1, w2, b2, g2, be2);
    conv_kernel<<<NBLK, NTHR, SMEM_FLOATS * sizeof(float)>>>(features, basis, w3, out);
}